// round 16
// baseline (speedup 1.0000x reference)
#include <cuda_runtime.h>
#include <cuda_fp16.h>
#include <cuda_pipeline.h>
#include <mma.h>
#include <cstdint>

using namespace nvcuda;

// Problem dims (fixed)
#define Td  4
#define Bd  32
#define Cd  512
#define CVd 2048
#define Nd  256
#define NHd 8
#define DHd 64
#define DVd 256
#define TBd (Td*Bd)      // 128
#define Zd  (TBd*NHd)    // 1024
#define MQKV 3072        // concat q(512) + k(512) + v(2048)

// ---------------- static scratch ------------------------------------------------
__device__ __align__(256) __half g_xs  [(size_t)TBd*Cd  *Nd];  // x spikes
__device__ __align__(256) __half g_qkvp[(size_t)TBd*MQKV*Nd];  // concat pre-act fp16
__device__ __align__(256) __half g_qkvh[(size_t)TBd*MQKV*Nd];  // concat spikes fp16
__device__ __align__(256) __half g_kv  [(size_t)Zd*DHd*DVd];   // kv single fp16
__device__ __align__(256) __half g_oh  [(size_t)TBd*CVd*Nd];   // attn spikes [z][e][n]
__device__ __align__(256) __half g_wqkv[MQKV*Cd];
__device__ __align__(256) __half g_wp  [Cd*CVd];
__device__ __align__(256) float g_b2d_qkv[MQKV*128];
__device__ __align__(256) float g_b2d_p  [Cd*128];

// ---------------- prep ----------------------------------------------------------
__global__ void prep_w1(const float* __restrict__ w, const float* __restrict__ scale,
                        __half* __restrict__ dst, int M, int K)
{
    int i = blockIdx.x * blockDim.x + threadIdx.x;
    if (i >= M * K) return;
    dst[i] = __float2half_rn(w[i] * scale[i / K]);
}

__global__ void prep_b(const float* __restrict__ bias, float* __restrict__ b2d, int M)
{
    int i = blockIdx.x * blockDim.x + threadIdx.x;
    if (i >= M * 128) return;
    b2d[i] = bias[i >> 7];
}

// ---------------- SFA scan, fp32 in -> fp16 spikes (x pass) ---------------------
__global__ void sfa_f2h4(const float4* __restrict__ in, uint2* __restrict__ out, int perT4)
{
    int i = blockIdx.x * blockDim.x + threadIdx.x;
    if (i >= perT4) return;
    float h0 = 0.f, h1 = 0.f, h2 = 0.f, h3 = 0.f;
#pragma unroll
    for (int t = 0; t < Td; ++t) {
        float4 v = in[(size_t)t * perT4 + i];
        float u0 = h0 + v.x, u1 = h1 + v.y, u2 = h2 + v.z, u3 = h3 + v.w;
        float s0 = rintf(fminf(fmaxf(u0, 0.f), 8.f));
        float s1 = rintf(fminf(fmaxf(u1, 0.f), 8.f));
        float s2 = rintf(fminf(fmaxf(u2, 0.f), 8.f));
        float s3 = rintf(fminf(fmaxf(u3, 0.f), 8.f));
        h0 = u0 - s0; h1 = u1 - s1; h2 = u2 - s2; h3 = u3 - s3;
        __half2 lo = __floats2half2_rn(s0 * 0.125f, s1 * 0.125f);
        __half2 hi = __floats2half2_rn(s2 * 0.125f, s3 * 0.125f);
        uint2 o;
        o.x = *(const unsigned*)&lo;
        o.y = *(const unsigned*)&hi;
        out[(size_t)t * perT4 + i] = o;
    }
}

// ---------------- SFA scan, fp16 pre-act in -> fp16 spikes out ------------------
__global__ void sfa_h2h4(const uint2* __restrict__ in, uint2* __restrict__ out, int perT4)
{
    int i = blockIdx.x * blockDim.x + threadIdx.x;
    if (i >= perT4) return;
    float h0 = 0.f, h1 = 0.f, h2 = 0.f, h3 = 0.f;
#pragma unroll
    for (int t = 0; t < Td; ++t) {
        uint2 v = in[(size_t)t * perT4 + i];
        float2 a = __half22float2(*(const __half2*)&v.x);
        float2 b = __half22float2(*(const __half2*)&v.y);
        float u0 = h0 + a.x, u1 = h1 + a.y, u2 = h2 + b.x, u3 = h3 + b.y;
        float s0 = rintf(fminf(fmaxf(u0, 0.f), 8.f));
        float s1 = rintf(fminf(fmaxf(u1, 0.f), 8.f));
        float s2 = rintf(fminf(fmaxf(u2, 0.f), 8.f));
        float s3 = rintf(fminf(fmaxf(u3, 0.f), 8.f));
        h0 = u0 - s0; h1 = u1 - s1; h2 = u2 - s2; h3 = u3 - s3;
        __half2 lo = __floats2half2_rn(s0 * 0.125f, s1 * 0.125f);
        __half2 hi = __floats2half2_rn(s2 * 0.125f, s3 * 0.125f);
        uint2 o;
        o.x = *(const unsigned*)&lo;
        o.y = *(const unsigned*)&hi;
        out[(size_t)t * perT4 + i] = o;
    }
}

// ---------------- conv GEMM: tile 128m x 256n (full N), BK=64, 2-stage ----------
// 8 warps (2 rows x 4 cols), warp tile 64x64 -> 16 MMA per 8 fragment loads.
static constexpr int C_OFF_B = 18432;            // A: 128x72 halves
static constexpr int C_ST    = 18432 + 33792;    // + B: 64x264 halves = 52224 B
static constexpr int C_SMEM  = 2 * C_ST;         // 104448 B -> 1 CTA/SM

template<bool HOUT>
__global__ void __launch_bounds__(256)
conv_wide(const __half* __restrict__ A, const __half* __restrict__ Ball,
          const float* __restrict__ b2d, void* __restrict__ Yall, int M, int K)
{
    extern __shared__ __align__(256) unsigned char sm[];

    const int tid = threadIdx.x;
    const int warp = tid >> 5, lane = tid & 31;
    const int wy = warp >> 2, wx = warp & 3;      // 2 x 4 warps
    const int mBase = blockIdx.y * 128;

    const __half* B = Ball + (size_t)blockIdx.z * K * Nd;

    const int ar = tid >> 1, ac = (tid & 1) * 32;   // A: 128 rows x 64 halves
    const int br = tid >> 2, bc = (tid & 3) * 64;   // B: 64 rows x 256 halves

    auto load_stage = [&](int s, int kb) {
        __half* ah = (__half*)(sm + s * C_ST);
        __half* bb = (__half*)(sm + s * C_ST + C_OFF_B);
        const __half* ga = A + (size_t)(mBase + ar) * K + kb + ac;
#pragma unroll
        for (int q = 0; q < 4; ++q)
            __pipeline_memcpy_async(ah + ar * 72 + ac + q * 8, ga + q * 8, 16);
        const __half* gb = B + (size_t)(kb + br) * Nd + bc;
#pragma unroll
        for (int q = 0; q < 8; ++q)
            __pipeline_memcpy_async(bb + br * 264 + bc + q * 8, gb + q * 8, 16);
    };

    wmma::fragment<wmma::accumulator, 16, 16, 16, float> acc[4][4];
#pragma unroll
    for (int i = 0; i < 4; ++i)
#pragma unroll
        for (int j = 0; j < 4; ++j)
            wmma::load_matrix_sync(acc[i][j],
                b2d + (size_t)(mBase + wy * 64 + i * 16) * 128 + j * 16,
                128, wmma::mem_row_major);   // b2d row-constant: any 16-col window

    load_stage(0, 0);
    __pipeline_commit();

    int rs = 0;
    for (int kb = 0; kb < K; kb += 64) {
        __pipeline_wait_prior(0);
        __syncthreads();

        int nk = kb + 64;
        if (nk < K) load_stage(rs ^ 1, nk);
        __pipeline_commit();

        const __half* ahp = (const __half*)(sm + rs * C_ST);
        const __half* bbp = (const __half*)(sm + rs * C_ST + C_OFF_B);
#pragma unroll
        for (int kk = 0; kk < 64; kk += 16) {
            wmma::fragment<wmma::matrix_a, 16, 16, 16, half, wmma::row_major> af[4];
#pragma unroll
            for (int i = 0; i < 4; ++i)
                wmma::load_matrix_sync(af[i], ahp + (wy * 64 + i * 16) * 72 + kk, 72);
#pragma unroll
            for (int j = 0; j < 4; ++j) {
                wmma::fragment<wmma::matrix_b, 16, 16, 16, half, wmma::row_major> bf;
                wmma::load_matrix_sync(bf, bbp + kk * 264 + wx * 64 + j * 16, 264);
#pragma unroll
                for (int i = 0; i < 4; ++i)
                    wmma::mma_sync(acc[i][j], af[i], bf, acc[i][j]);
            }
        }

        rs ^= 1;
    }

    if (HOUT) {
        __syncthreads();                 // smem tiles no longer needed
        float* st = (float*)sm + warp * (32 * 36);
        __half* Y = (__half*)Yall + (size_t)blockIdx.z * M * Nd;
#pragma unroll
        for (int ci = 0; ci < 4; ++ci) {
            const int i0 = (ci >> 1) * 2, j0 = (ci & 1) * 2;
#pragma unroll
            for (int ii = 0; ii < 2; ++ii)
#pragma unroll
                for (int jj = 0; jj < 2; ++jj)
                    wmma::store_matrix_sync(st + (ii * 16) * 36 + jj * 16,
                                            acc[i0 + ii][j0 + jj], 36, wmma::mem_row_major);
            __syncwarp();
            const int mRow = mBase + wy * 64 + i0 * 16 + lane;
            const int nCol = wx * 64 + j0 * 16;
            __align__(16) __half tmp[32];
#pragma unroll
            for (int c = 0; c < 32; ++c) tmp[c] = __float2half_rn(st[lane * 36 + c]);
            __half* yp = Y + (size_t)mRow * Nd + nCol;
#pragma unroll
            for (int c = 0; c < 4; ++c) ((uint4*)yp)[c] = ((const uint4*)tmp)[c];
            __syncwarp();
        }
    } else {
        float* Y = (float*)Yall + (size_t)blockIdx.z * M * Nd;
#pragma unroll
        for (int i = 0; i < 4; ++i)
#pragma unroll
            for (int j = 0; j < 4; ++j)
                wmma::store_matrix_sync(
                    Y + (size_t)(mBase + wy * 64 + i * 16) * Nd + wx * 64 + j * 16,
                    acc[i][j], Nd, wmma::mem_row_major);
    }
}

// ---------------- kv = K V^T -> single fp16 (rn) --------------------------------
__global__ void __launch_bounds__(256)
kv_wmma()
{
    __shared__ __align__(16) float stg[8][16 * 68];

    const int tid = threadIdx.x, warp = tid >> 5, lane = tid & 31;
    const int wy = warp >> 1, wx = warp & 1;
    const int z = blockIdx.x;
    const int tb = z >> 3, h = z & 7;

    const __half* Kp = g_qkvh + ((size_t)tb * MQKV + 512  + h * DHd) * Nd;
    const __half* Vp = g_qkvh + ((size_t)tb * MQKV + 1024 + h * DVd) * Nd;
    __half* KV = g_kv + (size_t)z * DHd * DVd;

    wmma::fragment<wmma::accumulator, 16, 16, 16, float> acc[8];
#pragma unroll
    for (int j = 0; j < 8; ++j) wmma::fill_fragment(acc[j], 0.f);

    for (int k0 = 0; k0 < Nd; k0 += 16) {
        wmma::fragment<wmma::matrix_a, 16, 16, 16, half, wmma::row_major> a;
        wmma::load_matrix_sync(a, Kp + (size_t)(wy * 16) * Nd + k0, Nd);
#pragma unroll
        for (int j = 0; j < 8; ++j) {
            wmma::fragment<wmma::matrix_b, 16, 16, 16, half, wmma::col_major> b;
            wmma::load_matrix_sync(b, Vp + (size_t)(wx * 128 + j * 16) * Nd + k0, Nd);
            wmma::mma_sync(acc[j], a, b, acc[j]);
        }
    }

    float* st = stg[warp];
#pragma unroll
    for (int ch = 0; ch < 2; ++ch) {
#pragma unroll
        for (int j = 0; j < 4; ++j)
            wmma::store_matrix_sync(st + j * 16, acc[ch * 4 + j], 68, wmma::mem_row_major);
        __syncwarp();
        const int r = lane & 15, cs = (lane >> 4) * 32;
        __align__(16) __half tH[32];
#pragma unroll
        for (int c = 0; c < 32; ++c) tH[c] = __float2half_rn(st[r * 68 + cs + c]);
        size_t off = (size_t)(wy * 16 + r) * DVd + wx * 128 + ch * 64 + cs;
#pragma unroll
        for (int c = 0; c < 4; ++c) ((uint4*)(KV + off))[c] = ((const uint4*)tH)[c];
        __syncwarp();
    }
}

// ---------------- attention O = 0.25 * kv^T Q, fused SFA -> oh ------------------
__global__ void __launch_bounds__(256)
av_fused()
{
    __shared__ __align__(16) float stg[8][32 * 36];

    const int tid = threadIdx.x, warp = tid >> 5, lane = tid & 31;
    const int wy = warp >> 1, wx = warp & 1;
    const int zp = blockIdx.z;
    const int b = zp >> 3, hd = zp & 7;
    const int eBase = blockIdx.y * 128, nBase = blockIdx.x * 64;

    float* st = stg[warp];
    const int eRow = eBase + wy * 32 + lane;

    float hreg[32];
#pragma unroll
    for (int c = 0; c < 32; ++c) hreg[c] = 0.f;

    for (int t = 0; t < Td; ++t) {
        const int tb = t * Bd + b;
        const __half* KV = g_kv + (size_t)(tb * NHd + hd) * DHd * DVd;
        const __half* Qp = g_qkvh + ((size_t)tb * MQKV + hd * DHd) * Nd;

        wmma::fragment<wmma::accumulator, 16, 16, 16, float> acc[2][2];
#pragma unroll
        for (int i = 0; i < 2; ++i)
#pragma unroll
            for (int j = 0; j < 2; ++j) wmma::fill_fragment(acc[i][j], 0.f);

#pragma unroll
        for (int k0 = 0; k0 < DHd; k0 += 16) {
            wmma::fragment<wmma::matrix_a, 16, 16, 16, half, wmma::col_major> ah[2];
#pragma unroll
            for (int i = 0; i < 2; ++i)
                wmma::load_matrix_sync(ah[i], KV + (size_t)k0 * DVd + eBase + wy * 32 + i * 16, DVd);
#pragma unroll
            for (int j = 0; j < 2; ++j) {
                wmma::fragment<wmma::matrix_b, 16, 16, 16, half, wmma::row_major> bf;
                wmma::load_matrix_sync(bf, Qp + (size_t)k0 * Nd + nBase + wx * 32 + j * 16, Nd);
#pragma unroll
                for (int i = 0; i < 2; ++i)
                    wmma::mma_sync(acc[i][j], ah[i], bf, acc[i][j]);
            }
        }

#pragma unroll
        for (int i = 0; i < 2; ++i)
#pragma unroll
            for (int j = 0; j < 2; ++j)
                wmma::store_matrix_sync(st + (i * 16) * 36 + j * 16, acc[i][j], 36,
                                        wmma::mem_row_major);
        __syncwarp();

        __align__(16) __half tmp[32];
#pragma unroll
        for (int c = 0; c < 32; ++c) {
            float u = hreg[c] + st[lane * 36 + c] * 0.25f;
            float s = rintf(fminf(fmaxf(u, 0.f), 8.f));
            hreg[c] = u - s;
            tmp[c] = __float2half_rn(s * 0.125f);
        }
        __half* yp = g_oh + ((size_t)tb * CVd + hd * DVd + eRow) * Nd + nBase + wx * 32;
#pragma unroll
        for (int c = 0; c < 4; ++c) ((uint4*)yp)[c] = ((const uint4*)tmp)[c];
        __syncwarp();
    }
}

// ---------------- launch --------------------------------------------------------
extern "C" void kernel_launch(void* const* d_in, const int* in_sizes, int n_in,
                              void* d_out, int out_size)
{
    (void)in_sizes; (void)n_in; (void)out_size;

    const float* x       = (const float*)d_in[0];
    const float* wq      = (const float*)d_in[1];
    const float* wk      = (const float*)d_in[2];
    const float* wv      = (const float*)d_in[3];
    const float* wp      = (const float*)d_in[4];
    const float* q_scale = (const float*)d_in[5];
    const float* q_bias  = (const float*)d_in[6];
    const float* k_scale = (const float*)d_in[7];
    const float* k_bias  = (const float*)d_in[8];
    const float* v_scale = (const float*)d_in[9];
    const float* v_bias  = (const float*)d_in[10];
    const float* p_scale = (const float*)d_in[11];
    const float* p_bias  = (const float*)d_in[12];
    float* out = (float*)d_out;

    void* p;
    cudaGetSymbolAddress(&p, g_xs);      __half* xs   = (__half*)p;
    cudaGetSymbolAddress(&p, g_qkvp);    __half* qkvp = (__half*)p;
    cudaGetSymbolAddress(&p, g_qkvh);    __half* qkvh = (__half*)p;
    cudaGetSymbolAddress(&p, g_oh);      __half* oh   = (__half*)p;
    cudaGetSymbolAddress(&p, g_wqkv);    __half* wqkv = (__half*)p;
    cudaGetSymbolAddress(&p, g_wp);      __half* wpp  = (__half*)p;
    cudaGetSymbolAddress(&p, g_b2d_qkv); float*  b2a  = (float*)p;
    cudaGetSymbolAddress(&p, g_b2d_p);   float*  b2p  = (float*)p;

    cudaFuncSetAttribute(conv_wide<true>,  cudaFuncAttributeMaxDynamicSharedMemorySize, C_SMEM);
    cudaFuncSetAttribute(conv_wide<false>, cudaFuncAttributeMaxDynamicSharedMemorySize, C_SMEM);

    const int perT1 = Bd * Cd   * Nd;   //  4,194,304
    const int perTA = Bd * MQKV * Nd;   // 25,165,824 (concat qkv)

    // 0. weight folding into concat buffer + bias broadcast tables
    prep_w1<<<(Cd  * Cd  + 255) / 256, 256>>>(wq, q_scale, wqkv,             Cd,  Cd);
    prep_w1<<<(Cd  * Cd  + 255) / 256, 256>>>(wk, k_scale, wqkv + 512 * Cd,  Cd,  Cd);
    prep_w1<<<(CVd * Cd  + 255) / 256, 256>>>(wv, v_scale, wqkv + 1024 * Cd, CVd, Cd);
    prep_w1<<<(Cd  * CVd + 255) / 256, 256>>>(wp, p_scale, wpp,              Cd,  CVd);
    prep_b<<<(Cd  * 128 + 255) / 256, 256>>>(q_bias, b2a,              Cd);
    prep_b<<<(Cd  * 128 + 255) / 256, 256>>>(k_bias, b2a + 512 * 128,  Cd);
    prep_b<<<(CVd * 128 + 255) / 256, 256>>>(v_bias, b2a + 1024 * 128, CVd);
    prep_b<<<(Cd  * 128 + 255) / 256, 256>>>(p_bias, b2p,              Cd);

    // 1. head spikes (fp16)
    sfa_f2h4<<<perT1 / 4 / 256, 256>>>((const float4*)x, (uint2*)xs, perT1 / 4);

    // 2. merged q/k/v conv + BN -> fp16 pre-activations (128x256 tiles)
    conv_wide<true><<<dim3(1, MQKV / 128, TBd), 256, C_SMEM>>>(wqkv, xs, b2a, qkvp, MQKV, Cd);

    // 3. merged spike pass
    sfa_h2h4<<<perTA / 4 / 256, 256>>>((const uint2*)qkvp, (uint2*)qkvh, perTA / 4);

    // 4. linear attention: kv single fp16, O = 0.25 kv^T Q fused SFA
    kv_wmma<<<Zd, 256>>>();
    av_fused<<<dim3(4, 2, Bd * NHd), 256>>>();

    // 5. projection conv + BN -> fp32 output
    conv_wide<false><<<dim3(1, 4, TBd), 256, C_SMEM>>>(wpp, oh, b2p, out, Cd, CVd);
}

// round 17
// speedup vs baseline: 1.0601x; 1.0601x over previous
#include <cuda_runtime.h>
#include <cuda_fp16.h>
#include <cuda_pipeline.h>
#include <mma.h>
#include <cstdint>

using namespace nvcuda;

// Problem dims (fixed)
#define Td  4
#define Bd  32
#define Cd  512
#define CVd 2048
#define Nd  256
#define NHd 8
#define DHd 64
#define DVd 256
#define TBd (Td*Bd)      // 128
#define Zd  (TBd*NHd)    // 1024
#define MQKV 3072        // concat q(512) + k(512) + v(2048)

// ---------------- static scratch ------------------------------------------------
__device__ __align__(256) __half g_xs  [(size_t)TBd*Cd  *Nd];  // x spikes
__device__ __align__(256) __half g_qkvh[(size_t)TBd*MQKV*Nd];  // concat spikes fp16
__device__ __align__(256) __half g_kv  [(size_t)Zd*DHd*DVd];   // kv single fp16
__device__ __align__(256) __half g_oh  [(size_t)TBd*CVd*Nd];   // attn spikes [z][e][n]
__device__ __align__(256) __half g_wqkv[MQKV*Cd];
__device__ __align__(256) __half g_wp  [Cd*CVd];
__device__ __align__(256) float  g_b2d_p[Cd*128];

// ---------------- prep ----------------------------------------------------------
__global__ void prep_w1(const float* __restrict__ w, const float* __restrict__ scale,
                        __half* __restrict__ dst, int M, int K)
{
    int i = blockIdx.x * blockDim.x + threadIdx.x;
    if (i >= M * K) return;
    dst[i] = __float2half_rn(w[i] * scale[i / K]);
}

__global__ void prep_b(const float* __restrict__ bias, float* __restrict__ b2d, int M)
{
    int i = blockIdx.x * blockDim.x + threadIdx.x;
    if (i >= M * 128) return;
    b2d[i] = bias[i >> 7];
}

// ---------------- SFA scan, fp32 in -> fp16 spikes (x pass) ---------------------
__global__ void sfa_f2h4(const float4* __restrict__ in, uint2* __restrict__ out, int perT4)
{
    int i = blockIdx.x * blockDim.x + threadIdx.x;
    if (i >= perT4) return;
    float h0 = 0.f, h1 = 0.f, h2 = 0.f, h3 = 0.f;
#pragma unroll
    for (int t = 0; t < Td; ++t) {
        float4 v = in[(size_t)t * perT4 + i];
        float u0 = h0 + v.x, u1 = h1 + v.y, u2 = h2 + v.z, u3 = h3 + v.w;
        float s0 = rintf(fminf(fmaxf(u0, 0.f), 8.f));
        float s1 = rintf(fminf(fmaxf(u1, 0.f), 8.f));
        float s2 = rintf(fminf(fmaxf(u2, 0.f), 8.f));
        float s3 = rintf(fminf(fmaxf(u3, 0.f), 8.f));
        h0 = u0 - s0; h1 = u1 - s1; h2 = u2 - s2; h3 = u3 - s3;
        __half2 lo = __floats2half2_rn(s0 * 0.125f, s1 * 0.125f);
        __half2 hi = __floats2half2_rn(s2 * 0.125f, s3 * 0.125f);
        uint2 o;
        o.x = *(const unsigned*)&lo;
        o.y = *(const unsigned*)&hi;
        out[(size_t)t * perT4 + i] = o;
    }
}

// ---------------- fused qkv conv + bias + SFA: tile 128x128, BK=64, t-loop ------
// For fixed b: loop t, Y_t = W[m][k] @ xs_t[k][n] + bias[m], SFA in epilogue.
// 8 warps (4x2), warp tile 32x64. Membrane in registers (lane owns 64 elems).
// smem: 2 pipeline stages + separate warp-local epilogue stage (overlap prefetch).
static constexpr int F_OFF_B = 18432;                // A: 128x72 halves
static constexpr int F_ST    = 35840;                // + B: 64x136 halves
static constexpr int F_STAGE = 2 * F_ST;             // 71680
static constexpr int F_SMEM  = F_STAGE + 8 * 32 * 36 * 4;   // + 36864 = 108544 B

__global__ void __launch_bounds__(256, 1)
conv_sfa(const __half* __restrict__ A, const __half* __restrict__ Ball,
         const float* __restrict__ qb, const float* __restrict__ kb_,
         const float* __restrict__ vb, __half* __restrict__ Yall)
{
    extern __shared__ __align__(256) unsigned char sm[];
    float* stg = (float*)(sm + F_STAGE);

    const int tid = threadIdx.x;
    const int warp = tid >> 5, lane = tid & 31;
    const int wy = warp >> 1, wx = warp & 1;
    const int mBase = blockIdx.y * 128, nBase = blockIdx.x * 128;
    const int b = blockIdx.z;
    const int K = Cd;

    const int ar = tid >> 1, ac = (tid & 1) * 32;    // A: 128 rows x 64 k
    const int br = tid >> 2, bc = (tid & 3) * 32;    // B: 64 k x 128 n

    auto load_stage = [&](int s, int t, int kb) {
        __half* ah = (__half*)(sm + s * F_ST);
        __half* bb = (__half*)(sm + s * F_ST + F_OFF_B);
        const __half* ga = A + (size_t)(mBase + ar) * K + kb + ac;
#pragma unroll
        for (int q = 0; q < 4; ++q)
            __pipeline_memcpy_async(ah + ar * 72 + ac + q * 8, ga + q * 8, 16);
        const __half* gb = Ball + (size_t)(t * Bd + b) * K * Nd
                           + (size_t)(kb + br) * Nd + nBase + bc;
#pragma unroll
        for (int q = 0; q < 4; ++q)
            __pipeline_memcpy_async(bb + br * 136 + bc + q * 8, gb + q * 8, 16);
    };

    // per-lane bias for the row this lane owns in the epilogue
    const int mRow = mBase + wy * 32 + lane;
    float bv;
    if (mRow < 512)       bv = qb[mRow];
    else if (mRow < 1024) bv = kb_[mRow - 512];
    else                  bv = vb[mRow - 1024];

    float hreg[64];
#pragma unroll
    for (int c = 0; c < 64; ++c) hreg[c] = 0.f;

    float* st = stg + warp * (32 * 36);

    load_stage(0, 0, 0);
    __pipeline_commit();
    int rs = 0;

    for (int t = 0; t < Td; ++t) {
        wmma::fragment<wmma::accumulator, 16, 16, 16, float> acc[2][4];
#pragma unroll
        for (int i = 0; i < 2; ++i)
#pragma unroll
            for (int j = 0; j < 4; ++j) wmma::fill_fragment(acc[i][j], 0.f);

        for (int kb = 0; kb < K; kb += 64) {
            __pipeline_wait_prior(0);
            __syncthreads();

            int nt = t, nk = kb + 64;
            if (nk == K) { nt = t + 1; nk = 0; }
            if (nt < Td) load_stage(rs ^ 1, nt, nk);
            __pipeline_commit();

            const __half* ahp = (const __half*)(sm + rs * F_ST);
            const __half* bbp = (const __half*)(sm + rs * F_ST + F_OFF_B);
#pragma unroll
            for (int kk = 0; kk < 64; kk += 16) {
                wmma::fragment<wmma::matrix_a, 16, 16, 16, half, wmma::row_major> ah[2];
#pragma unroll
                for (int i = 0; i < 2; ++i)
                    wmma::load_matrix_sync(ah[i], ahp + (wy * 32 + i * 16) * 72 + kk, 72);
#pragma unroll
                for (int j = 0; j < 4; ++j) {
                    wmma::fragment<wmma::matrix_b, 16, 16, 16, half, wmma::row_major> bf;
                    wmma::load_matrix_sync(bf, bbp + kk * 136 + wx * 64 + j * 16, 136);
#pragma unroll
                    for (int i = 0; i < 2; ++i)
                        wmma::mma_sync(acc[i][j], ah[i], bf, acc[i][j]);
                }
            }

            rs ^= 1;
        }

        // epilogue (warp-local stage region; overlaps the already-issued prefetch)
        __half* Y = Yall + (size_t)(t * Bd + b) * MQKV * Nd;
#pragma unroll
        for (int ch = 0; ch < 2; ++ch) {
#pragma unroll
            for (int i = 0; i < 2; ++i)
#pragma unroll
                for (int jj = 0; jj < 2; ++jj)
                    wmma::store_matrix_sync(st + (i * 16) * 36 + jj * 16,
                                            acc[i][ch * 2 + jj], 36, wmma::mem_row_major);
            __syncwarp();
            __align__(16) __half tmp[32];
#pragma unroll
            for (int c = 0; c < 32; ++c) {
                float u = hreg[ch * 32 + c] + st[lane * 36 + c] + bv;
                float s = rintf(fminf(fmaxf(u, 0.f), 8.f));
                hreg[ch * 32 + c] = u - s;
                tmp[c] = __float2half_rn(s * 0.125f);
            }
            __half* yp = Y + (size_t)mRow * Nd + nBase + wx * 64 + ch * 32;
#pragma unroll
            for (int c = 0; c < 4; ++c) ((uint4*)yp)[c] = ((const uint4*)tmp)[c];
            __syncwarp();
        }
    }
}

// ---------------- p conv: single-term fp16, BK=64, 2-stage (R14, unchanged) -----
static constexpr int P_OFF_B = 18432;
static constexpr int P_ST    = 35840;
static constexpr int P_SMEM  = 2 * P_ST;             // 71680 B -> 2 CTAs/SM

__global__ void __launch_bounds__(256)
conv_wmma1(const __half* __restrict__ A, const __half* __restrict__ Ball,
           const float* __restrict__ b2d, float* __restrict__ Yall, int M, int K)
{
    extern __shared__ __align__(256) unsigned char sm[];

    const int tid = threadIdx.x;
    const int warp = tid >> 5;
    const int wy = warp >> 1, wx = warp & 1;
    const int mBase = blockIdx.y * 128, nBase = blockIdx.x * 128;

    const __half* B = Ball + (size_t)blockIdx.z * K * Nd;
    float*        Y = Yall + (size_t)blockIdx.z * M * Nd;

    const int ar = tid >> 1, ac = (tid & 1) * 32;
    const int br = tid >> 2, bc = (tid & 3) * 32;

    auto load_stage = [&](int s, int kb) {
        __half* ah = (__half*)(sm + s * P_ST);
        __half* bb = (__half*)(sm + s * P_ST + P_OFF_B);
        const __half* ga = A + (size_t)(mBase + ar) * K + kb + ac;
#pragma unroll
        for (int q = 0; q < 4; ++q)
            __pipeline_memcpy_async(ah + ar * 72 + ac + q * 8, ga + q * 8, 16);
        const __half* gb = B + (size_t)(kb + br) * Nd + nBase + bc;
#pragma unroll
        for (int q = 0; q < 4; ++q)
            __pipeline_memcpy_async(bb + br * 136 + bc + q * 8, gb + q * 8, 16);
    };

    wmma::fragment<wmma::accumulator, 16, 16, 16, float> acc[2][4];
#pragma unroll
    for (int i = 0; i < 2; ++i)
#pragma unroll
        for (int j = 0; j < 4; ++j)
            wmma::load_matrix_sync(acc[i][j],
                b2d + (size_t)(mBase + wy * 32 + i * 16) * 128 + wx * 64 + j * 16,
                128, wmma::mem_row_major);

    load_stage(0, 0);
    __pipeline_commit();

    int rs = 0;
    for (int kb = 0; kb < K; kb += 64) {
        __pipeline_wait_prior(0);
        __syncthreads();

        int nk = kb + 64;
        if (nk < K) load_stage(rs ^ 1, nk);
        __pipeline_commit();

        const __half* ahp = (const __half*)(sm + rs * P_ST);
        const __half* bbp = (const __half*)(sm + rs * P_ST + P_OFF_B);
#pragma unroll
        for (int kk = 0; kk < 64; kk += 16) {
            wmma::fragment<wmma::matrix_a, 16, 16, 16, half, wmma::row_major> ah[2];
#pragma unroll
            for (int i = 0; i < 2; ++i)
                wmma::load_matrix_sync(ah[i], ahp + (wy * 32 + i * 16) * 72 + kk, 72);
#pragma unroll
            for (int j = 0; j < 4; ++j) {
                wmma::fragment<wmma::matrix_b, 16, 16, 16, half, wmma::row_major> bf;
                wmma::load_matrix_sync(bf, bbp + kk * 136 + wx * 64 + j * 16, 136);
#pragma unroll
                for (int i = 0; i < 2; ++i)
                    wmma::mma_sync(acc[i][j], ah[i], bf, acc[i][j]);
            }
        }

        rs ^= 1;
    }

#pragma unroll
    for (int i = 0; i < 2; ++i)
#pragma unroll
        for (int j = 0; j < 4; ++j)
            wmma::store_matrix_sync(
                Y + (size_t)(mBase + wy * 32 + i * 16) * Nd + nBase + wx * 64 + j * 16,
                acc[i][j], Nd, wmma::mem_row_major);
}

// ---------------- kv = K V^T -> single fp16 (concat offsets) --------------------
__global__ void __launch_bounds__(256)
kv_wmma()
{
    __shared__ __align__(16) float stg[8][16 * 68];

    const int tid = threadIdx.x, warp = tid >> 5, lane = tid & 31;
    const int wy = warp >> 1, wx = warp & 1;
    const int z = blockIdx.x;
    const int tb = z >> 3, h = z & 7;

    const __half* Kp = g_qkvh + ((size_t)tb * MQKV + 512  + h * DHd) * Nd;
    const __half* Vp = g_qkvh + ((size_t)tb * MQKV + 1024 + h * DVd) * Nd;
    __half* KV = g_kv + (size_t)z * DHd * DVd;

    wmma::fragment<wmma::accumulator, 16, 16, 16, float> acc[8];
#pragma unroll
    for (int j = 0; j < 8; ++j) wmma::fill_fragment(acc[j], 0.f);

    for (int k0 = 0; k0 < Nd; k0 += 16) {
        wmma::fragment<wmma::matrix_a, 16, 16, 16, half, wmma::row_major> a;
        wmma::load_matrix_sync(a, Kp + (size_t)(wy * 16) * Nd + k0, Nd);
#pragma unroll
        for (int j = 0; j < 8; ++j) {
            wmma::fragment<wmma::matrix_b, 16, 16, 16, half, wmma::col_major> b;
            wmma::load_matrix_sync(b, Vp + (size_t)(wx * 128 + j * 16) * Nd + k0, Nd);
            wmma::mma_sync(acc[j], a, b, acc[j]);
        }
    }

    float* st = stg[warp];
#pragma unroll
    for (int ch = 0; ch < 2; ++ch) {
#pragma unroll
        for (int j = 0; j < 4; ++j)
            wmma::store_matrix_sync(st + j * 16, acc[ch * 4 + j], 68, wmma::mem_row_major);
        __syncwarp();
        const int r = lane & 15, cs = (lane >> 4) * 32;
        __align__(16) __half tH[32];
#pragma unroll
        for (int c = 0; c < 32; ++c) tH[c] = __float2half_rn(st[r * 68 + cs + c]);
        size_t off = (size_t)(wy * 16 + r) * DVd + wx * 128 + ch * 64 + cs;
#pragma unroll
        for (int c = 0; c < 4; ++c) ((uint4*)(KV + off))[c] = ((const uint4*)tH)[c];
        __syncwarp();
    }
}

// ---------------- attention O = 0.25 * kv^T Q, fused SFA -> oh ------------------
__global__ void __launch_bounds__(256)
av_fused()
{
    __shared__ __align__(16) float stg[8][32 * 36];

    const int tid = threadIdx.x, warp = tid >> 5, lane = tid & 31;
    const int wy = warp >> 1, wx = warp & 1;
    const int zp = blockIdx.z;
    const int b = zp >> 3, hd = zp & 7;
    const int eBase = blockIdx.y * 128, nBase = blockIdx.x * 64;

    float* st = stg[warp];
    const int eRow = eBase + wy * 32 + lane;

    float hreg[32];
#pragma unroll
    for (int c = 0; c < 32; ++c) hreg[c] = 0.f;

    for (int t = 0; t < Td; ++t) {
        const int tb = t * Bd + b;
        const __half* KV = g_kv + (size_t)(tb * NHd + hd) * DHd * DVd;
        const __half* Qp = g_qkvh + ((size_t)tb * MQKV + hd * DHd) * Nd;

        wmma::fragment<wmma::accumulator, 16, 16, 16, float> acc[2][2];
#pragma unroll
        for (int i = 0; i < 2; ++i)
#pragma unroll
            for (int j = 0; j < 2; ++j) wmma::fill_fragment(acc[i][j], 0.f);

#pragma unroll
        for (int k0 = 0; k0 < DHd; k0 += 16) {
            wmma::fragment<wmma::matrix_a, 16, 16, 16, half, wmma::col_major> ah[2];
#pragma unroll
            for (int i = 0; i < 2; ++i)
                wmma::load_matrix_sync(ah[i], KV + (size_t)k0 * DVd + eBase + wy * 32 + i * 16, DVd);
#pragma unroll
            for (int j = 0; j < 2; ++j) {
                wmma::fragment<wmma::matrix_b, 16, 16, 16, half, wmma::row_major> bf;
                wmma::load_matrix_sync(bf, Qp + (size_t)k0 * Nd + nBase + wx * 32 + j * 16, Nd);
#pragma unroll
                for (int i = 0; i < 2; ++i)
                    wmma::mma_sync(acc[i][j], ah[i], bf, acc[i][j]);
            }
        }

#pragma unroll
        for (int i = 0; i < 2; ++i)
#pragma unroll
            for (int j = 0; j < 2; ++j)
                wmma::store_matrix_sync(st + (i * 16) * 36 + j * 16, acc[i][j], 36,
                                        wmma::mem_row_major);
        __syncwarp();

        __align__(16) __half tmp[32];
#pragma unroll
        for (int c = 0; c < 32; ++c) {
            float u = hreg[c] + st[lane * 36 + c] * 0.25f;
            float s = rintf(fminf(fmaxf(u, 0.f), 8.f));
            hreg[c] = u - s;
            tmp[c] = __float2half_rn(s * 0.125f);
        }
        __half* yp = g_oh + ((size_t)tb * CVd + hd * DVd + eRow) * Nd + nBase + wx * 32;
#pragma unroll
        for (int c = 0; c < 4; ++c) ((uint4*)yp)[c] = ((const uint4*)tmp)[c];
        __syncwarp();
    }
}

// ---------------- launch --------------------------------------------------------
extern "C" void kernel_launch(void* const* d_in, const int* in_sizes, int n_in,
                              void* d_out, int out_size)
{
    (void)in_sizes; (void)n_in; (void)out_size;

    const float* x       = (const float*)d_in[0];
    const float* wq      = (const float*)d_in[1];
    const float* wk      = (const float*)d_in[2];
    const float* wv      = (const float*)d_in[3];
    const float* wp      = (const float*)d_in[4];
    const float* q_scale = (const float*)d_in[5];
    const float* q_bias  = (const float*)d_in[6];
    const float* k_scale = (const float*)d_in[7];
    const float* k_bias  = (const float*)d_in[8];
    const float* v_scale = (const float*)d_in[9];
    const float* v_bias  = (const float*)d_in[10];
    const float* p_scale = (const float*)d_in[11];
    const float* p_bias  = (const float*)d_in[12];
    float* out = (float*)d_out;

    void* p;
    cudaGetSymbolAddress(&p, g_xs);    __half* xs   = (__half*)p;
    cudaGetSymbolAddress(&p, g_qkvh);  __half* qkvh = (__half*)p;
    cudaGetSymbolAddress(&p, g_oh);    __half* oh   = (__half*)p;
    cudaGetSymbolAddress(&p, g_wqkv);  __half* wqkv = (__half*)p;
    cudaGetSymbolAddress(&p, g_wp);    __half* wpp  = (__half*)p;
    cudaGetSymbolAddress(&p, g_b2d_p); float*  b2p  = (float*)p;

    cudaFuncSetAttribute(conv_sfa,   cudaFuncAttributeMaxDynamicSharedMemorySize, F_SMEM);
    cudaFuncSetAttribute(conv_wmma1, cudaFuncAttributeMaxDynamicSharedMemorySize, P_SMEM);

    const int perT1 = Bd * Cd * Nd;   // 4,194,304

    // 0. weight folding into concat buffer + p bias table
    prep_w1<<<(Cd  * Cd  + 255) / 256, 256>>>(wq, q_scale, wqkv,             Cd,  Cd);
    prep_w1<<<(Cd  * Cd  + 255) / 256, 256>>>(wk, k_scale, wqkv + 512 * Cd,  Cd,  Cd);
    prep_w1<<<(CVd * Cd  + 255) / 256, 256>>>(wv, v_scale, wqkv + 1024 * Cd, CVd, Cd);
    prep_w1<<<(Cd  * CVd + 255) / 256, 256>>>(wp, p_scale, wpp,              Cd,  CVd);
    prep_b<<<(Cd * 128 + 255) / 256, 256>>>(p_bias, b2p, Cd);

    // 1. head spikes (fp16)
    sfa_f2h4<<<perT1 / 4 / 256, 256>>>((const float4*)x, (uint2*)xs, perT1 / 4);

    // 2. fused q/k/v conv + bias + SFA -> spikes directly (t-loop inside)
    conv_sfa<<<dim3(2, MQKV / 128, Bd), 256, F_SMEM>>>(wqkv, xs, q_bias, k_bias, v_bias, qkvh);

    // 3. linear attention: kv single fp16, O = 0.25 kv^T Q fused SFA
    kv_wmma<<<Zd, 256>>>();
    av_fused<<<dim3(4, 2, Bd * NHd), 256>>>();

    // 4. projection conv + BN -> fp32 output
    conv_wmma1<<<dim3(2, 4, TBd), 256, P_SMEM>>>(wpp, oh, b2p, out, Cd, CVd);
}